// round 13
// baseline (speedup 1.0000x reference)
#include <cuda_runtime.h>
#include <cuda_fp16.h>
#include <cstdint>
#include <math.h>

#define M_NODES 16384
#define IN_DIM  2048
#define HID_DIM 4096
#define OUT_DIM 2048

#define TILE_BYTES 16384          // 128 rows x 64 halves (128B), SW128-swizzled
#define NSTAGE 3
#define STAGE_BYTES (3 * TILE_BYTES)   // A tile (128 rows) + B slab (256 rows = 2 tiles)
#define SMEM_BYTES  (NSTAGE * STAGE_BYTES)

// ---------------------------------------------------------------------------
// fp16 scratch, tiled+swizzled layout (static device arrays -- no allocation)
// tile t = row_block*KT + k_chunk; byte(r,h) at t*16384 + SW128(r*128 + h*2)
// ---------------------------------------------------------------------------
__device__ __align__(1024) __half g_x [(size_t)M_NODES * IN_DIM];
__device__ __align__(1024) __half g_w1[(size_t)HID_DIM * IN_DIM];
__device__ __align__(1024) __half g_w2[(size_t)OUT_DIM * HID_DIM];
__device__ __align__(1024) __half g_h [(size_t)M_NODES * HID_DIM];

__device__ __forceinline__ uint32_t sw128(uint32_t off) { return off ^ ((off >> 3) & 0x70); }

__device__ __forceinline__ uint32_t h2u(__half2 h) {
    __half2_raw r = *reinterpret_cast<__half2_raw*>(&h);
    return (uint32_t)r.x | ((uint32_t)r.y << 16);
}

// ---------------------------------------------------------------------------
// Conversion: fp32 row-major -> fp16 tiled+swizzled (granule = 16B = 8 halves)
// ---------------------------------------------------------------------------
__global__ void cvt_tiled(const float* __restrict__ src0, const int* __restrict__ idx,
                          size_t per_expert, __half* __restrict__ dst,
                          int K, int KT, size_t n_gran) {
    size_t g = (size_t)blockIdx.x * blockDim.x + threadIdx.x;
    if (g >= n_gran) return;
    const float* src = idx ? (src0 + (size_t)(*idx) * per_expert) : src0;
    uint32_t t  = (uint32_t)(g >> 10);
    uint32_t gi = (uint32_t)(g & 1023);
    uint32_t r  = gi >> 3, q = gi & 7;
    uint32_t rb = t / KT, c = t % KT;
    const float4* s = reinterpret_cast<const float4*>(
        src + ((size_t)rb * 128 + r) * K + (size_t)c * 64 + q * 8);
    float4 v0 = s[0], v1 = s[1];
    uint4 pack;
    pack.x = h2u(__floats2half2_rn(v0.x, v0.y));
    pack.y = h2u(__floats2half2_rn(v0.z, v0.w));
    pack.z = h2u(__floats2half2_rn(v1.x, v1.y));
    pack.w = h2u(__floats2half2_rn(v1.z, v1.w));
    uint32_t off = sw128(r * 128 + q * 16);
    *reinterpret_cast<uint4*>(reinterpret_cast<char*>(dst) + (size_t)t * TILE_BYTES + off) = pack;
}

// ---------------------------------------------------------------------------
// PTX wrappers
// ---------------------------------------------------------------------------
__device__ __forceinline__ void cp_async16(uint32_t saddr, const void* gaddr) {
    asm volatile("cp.async.cg.shared.global [%0], [%1], 16;\n" :: "r"(saddr), "l"(gaddr));
}
__device__ __forceinline__ void cp_commit() {
    asm volatile("cp.async.commit_group;\n");
}
template<int N>
__device__ __forceinline__ void cp_wait() {
    asm volatile("cp.async.wait_group %0;\n" :: "n"(N));
}
__device__ __forceinline__ void ldmatrix_x4(uint32_t& r0, uint32_t& r1,
                                            uint32_t& r2, uint32_t& r3, uint32_t addr) {
    asm volatile("ldmatrix.sync.aligned.m8n8.x4.shared.b16 {%0,%1,%2,%3}, [%4];"
                 : "=r"(r0), "=r"(r1), "=r"(r2), "=r"(r3) : "r"(addr));
}
__device__ __forceinline__ void mma_16816(float& d0, float& d1, float& d2, float& d3,
                                          uint32_t a0, uint32_t a1, uint32_t a2, uint32_t a3,
                                          uint32_t b0, uint32_t b1) {
    asm volatile("mma.sync.aligned.m16n8k16.row.col.f32.f16.f16.f32 "
                 "{%0,%1,%2,%3}, {%4,%5,%6,%7}, {%8,%9}, {%0,%1,%2,%3};"
                 : "+f"(d0), "+f"(d1), "+f"(d2), "+f"(d3)
                 : "r"(a0), "r"(a1), "r"(a2), "r"(a3), "r"(b0), "r"(b1));
}
__device__ __forceinline__ float gelu_erf(float v) {
    return 0.5f * v * (1.0f + erff(v * 0.70710678118654752f));
}

// ---------------------------------------------------------------------------
// GEMM: C[128x256 tile] = A[128,K] * B[256,K]^T, fp16 in / fp32 accum.
// A,B in tiled+swizzled gmem. 8 warps, warp tile 64x64, 1 CTA/SM.
// GELU=true: out = tiled-swizzled fp16 (KT_DST k-chunks per row-block).
// GELU=false: out = fp32 row-major, width OUT_DIM.
// ---------------------------------------------------------------------------
template<bool GELU>
__global__ __launch_bounds__(256, 1)
void hmma_gemm(const char* __restrict__ gA, const char* __restrict__ gB,
               void* __restrict__ out, int KT, int KT_DST)
{
    extern __shared__ __align__(128) char smem[];
    const uint32_t sbase = (uint32_t)__cvta_generic_to_shared(smem);

    const int tid  = threadIdx.x;
    const int warp = tid >> 5;
    const int lane = tid & 31;
    const int wm   = warp & 1;             // 0..1 : 64-row slab
    const int wn   = warp >> 1;            // 0..3 : 64-col slab
    const int bm   = blockIdx.y * 128;
    const int bn   = blockIdx.x * 256;

    const char* baseA  = gA + (size_t)blockIdx.y * KT * TILE_BYTES;
    const char* baseB0 = gB + (size_t)(blockIdx.x * 2) * KT * TILE_BYTES;
    const char* baseB1 = baseB0 + (size_t)KT * TILE_BYTES;

    float acc[4][8][4];
    #pragma unroll
    for (int i = 0; i < 4; i++)
        #pragma unroll
        for (int j = 0; j < 8; j++)
            #pragma unroll
            for (int r = 0; r < 4; r++) acc[i][j][r] = 0.0f;

    // ---- linear stage loader: 3072 granules of 16B, 12 per thread ----
    auto load_stage = [&](int kt, int s) {
        const uint32_t st = sbase + (uint32_t)s * STAGE_BYTES;
        const char* sA = baseA  + (size_t)kt * TILE_BYTES;
        const char* sB0 = baseB0 + (size_t)kt * TILE_BYTES;
        const char* sB1 = baseB1 + (size_t)kt * TILE_BYTES;
        #pragma unroll
        for (int i = 0; i < 4; i++) {
            uint32_t o = (uint32_t)(tid + i * 256) * 16;
            cp_async16(st + o, sA + o);
        }
        #pragma unroll
        for (int i = 0; i < 4; i++) {
            uint32_t o = (uint32_t)(tid + i * 256) * 16;
            cp_async16(st + TILE_BYTES + o, sB0 + o);
        }
        #pragma unroll
        for (int i = 0; i < 4; i++) {
            uint32_t o = (uint32_t)(tid + i * 256) * 16;
            cp_async16(st + 2 * TILE_BYTES + o, sB1 + o);
        }
        cp_commit();
    };

    // ---- precomputed ldmatrix base offsets ----
    // addr(r, c) = r*128 + (c ^ ((r&7)<<4)); c = fc2 | kk*32 (bit-disjoint)
    // so per-kk address = base ^ (kk*32).
    const uint32_t fc2 = (uint32_t)(lane >> 4) * 16;
    uint32_t rowA[4], rowB[4];
    #pragma unroll
    for (int mi = 0; mi < 4; mi++) {
        uint32_t r = wm * 64 + mi * 16 + (lane & 15);
        rowA[mi] = r * 128 + (fc2 ^ ((r & 7) << 4));
    }
    #pragma unroll
    for (int p = 0; p < 4; p++) {
        uint32_t r = wn * 64 + p * 16 + (lane & 15);
        rowB[p] = r * 128 + (fc2 ^ ((r & 7) << 4));
    }

    uint32_t af[2][4][4];
    uint32_t bf[2][4][4];

    load_stage(0, 0);
    if (KT > 1) load_stage(1, 1);

    int slot = 0, slot_next = (KT > 2) ? 2 : 0;
    for (int kt = 0; kt < KT; kt++) {
        if (kt + 1 < KT) cp_wait<1>(); else cp_wait<0>();
        __syncthreads();
        if (kt + 2 < KT) {
            load_stage(kt + 2, slot_next);
            slot_next = (slot_next == 2) ? 0 : slot_next + 1;
        }

        const uint32_t sa  = sbase + (uint32_t)slot * STAGE_BYTES;
        const uint32_t sbB = sa + TILE_BYTES;
        slot = (slot == 2) ? 0 : slot + 1;

        auto ldf = [&](int kk, int b) {
            const uint32_t kx = (uint32_t)kk * 32;
            #pragma unroll
            for (int mi = 0; mi < 4; mi++)
                ldmatrix_x4(af[b][mi][0], af[b][mi][1], af[b][mi][2], af[b][mi][3],
                            sa + (rowA[mi] ^ kx));
            #pragma unroll
            for (int p = 0; p < 4; p++)
                ldmatrix_x4(bf[b][p][0], bf[b][p][1], bf[b][p][2], bf[b][p][3],
                            sbB + (rowB[p] ^ kx));
        };

        ldf(0, 0);
        #pragma unroll
        for (int kk = 0; kk < 4; kk++) {
            if (kk < 3) ldf(kk + 1, (kk + 1) & 1);
            const int b = kk & 1;
            #pragma unroll
            for (int mi = 0; mi < 4; mi++) {
                #pragma unroll
                for (int p = 0; p < 4; p++) {
                    mma_16816(acc[mi][2*p][0], acc[mi][2*p][1], acc[mi][2*p][2], acc[mi][2*p][3],
                              af[b][mi][0], af[b][mi][1], af[b][mi][2], af[b][mi][3],
                              bf[b][p][0], bf[b][p][2]);
                    mma_16816(acc[mi][2*p+1][0], acc[mi][2*p+1][1], acc[mi][2*p+1][2], acc[mi][2*p+1][3],
                              af[b][mi][0], af[b][mi][1], af[b][mi][2], af[b][mi][3],
                              bf[b][p][1], bf[b][p][3]);
                }
            }
        }
    }

    // ---- epilogue ----
    const int qrow = lane >> 2;            // 0..7
    const int qcol = (lane & 3) * 2;       // 0,2,4,6
    #pragma unroll
    for (int mi = 0; mi < 4; mi++) {
        #pragma unroll
        for (int ni = 0; ni < 8; ni++) {
            float c0 = acc[mi][ni][0], c1 = acc[mi][ni][1];
            float c2 = acc[mi][ni][2], c3 = acc[mi][ni][3];
            int lrow = wm * 64 + mi * 16 + qrow;           // local row in 128-tile
            int col  = bn + wn * 64 + ni * 8 + qcol;       // global col
            if (GELU) {
                size_t tb = ((size_t)(bm >> 7) * KT_DST + (uint32_t)(col >> 6)) * TILE_BYTES;
                char* dst = (char*)out + tb;
                uint32_t cb = (uint32_t)(col & 63) * 2;
                __half2 v01 = __floats2half2_rn(gelu_erf(c0), gelu_erf(c1));
                __half2 v23 = __floats2half2_rn(gelu_erf(c2), gelu_erf(c3));
                *reinterpret_cast<__half2*>(dst + sw128((uint32_t)lrow * 128 + cb))       = v01;
                *reinterpret_cast<__half2*>(dst + sw128((uint32_t)(lrow + 8) * 128 + cb)) = v23;
            } else {
                float* o = (float*)out;
                size_t r0 = (size_t)(bm + lrow) * OUT_DIM + col;
                *reinterpret_cast<float2*>(o + r0)                       = make_float2(c0, c1);
                *reinterpret_cast<float2*>(o + r0 + (size_t)8 * OUT_DIM) = make_float2(c2, c3);
            }
        }
    }
}

// ---------------------------------------------------------------------------
// launch
// ---------------------------------------------------------------------------
extern "C" void kernel_launch(void* const* d_in, const int* in_sizes, int n_in,
                              void* d_out, int out_size) {
    const int*   d_idx = (const int*)  d_in[0];
    const float* d_x   = (const float*)d_in[1];
    const float* d_W1  = (const float*)d_in[2];
    const float* d_W2  = (const float*)d_in[3];

    __half *px, *pw1, *pw2, *ph;
    cudaGetSymbolAddress((void**)&px,  g_x);
    cudaGetSymbolAddress((void**)&pw1, g_w1);
    cudaGetSymbolAddress((void**)&pw2, g_w2);
    cudaGetSymbolAddress((void**)&ph,  g_h);

    cudaFuncSetAttribute(hmma_gemm<true>,  cudaFuncAttributeMaxDynamicSharedMemorySize, SMEM_BYTES);
    cudaFuncSetAttribute(hmma_gemm<false>, cudaFuncAttributeMaxDynamicSharedMemorySize, SMEM_BYTES);

    // 1) x -> tiled fp16 (KT=32)
    {
        size_t ng = (size_t)M_NODES * IN_DIM / 8;
        cvt_tiled<<<(unsigned)((ng + 255) / 256), 256>>>(d_x, nullptr, 0, px, IN_DIM, IN_DIM / 64, ng);
    }
    // 2) W1[e] -> tiled fp16 (KT=32)
    {
        size_t pe = (size_t)HID_DIM * IN_DIM;
        size_t ng = pe / 8;
        cvt_tiled<<<(unsigned)((ng + 255) / 256), 256>>>(d_W1, d_idx, pe, pw1, IN_DIM, IN_DIM / 64, ng);
    }
    // 3) W2[e] -> tiled fp16 (KT=64)
    {
        size_t pe = (size_t)OUT_DIM * HID_DIM;
        size_t ng = pe / 8;
        cvt_tiled<<<(unsigned)((ng + 255) / 256), 256>>>(d_W2, d_idx, pe, pw2, HID_DIM, HID_DIM / 64, ng);
    }
    // 4) h = gelu(x @ W1^T) -> tiled fp16, dst KT=64
    {
        dim3 grid(HID_DIM / 256, M_NODES / 128);
        hmma_gemm<true><<<grid, 256, SMEM_BYTES>>>((const char*)px, (const char*)pw1, ph,
                                                   IN_DIM / 64, HID_DIM / 64);
    }
    // 5) out = h @ W2^T -> fp32 row-major
    {
        dim3 grid(OUT_DIM / 256, M_NODES / 128);
        hmma_gemm<false><<<grid, 256, SMEM_BYTES>>>((const char*)ph, (const char*)pw2, d_out,
                                                    HID_DIM / 64, 0);
    }
}

// round 15
// speedup vs baseline: 1.0867x; 1.0867x over previous
#include <cuda_runtime.h>
#include <cuda_fp16.h>
#include <cstdint>
#include <math.h>

#define M_NODES 16384
#define IN_DIM  2048
#define HID_DIM 4096
#define OUT_DIM 2048

#define TILE_BYTES 16384          // 128 rows x 64 halves (128B), SW128-swizzled
#define NSTAGE 4
#define STAGE_BYTES (3 * TILE_BYTES)   // A tile (128 rows) + B slab (256 rows = 2 tiles)
#define SMEM_BYTES  (NSTAGE * STAGE_BYTES)   // 192 KB

// ---------------------------------------------------------------------------
// fp16 scratch, tiled+swizzled layout (static device arrays -- no allocation)
// tile t = row_block*KT + k_chunk; byte(r,h) at t*16384 + SW128(r*128 + h*2)
// ---------------------------------------------------------------------------
__device__ __align__(1024) __half g_x [(size_t)M_NODES * IN_DIM];
__device__ __align__(1024) __half g_w1[(size_t)HID_DIM * IN_DIM];
__device__ __align__(1024) __half g_w2[(size_t)OUT_DIM * HID_DIM];
__device__ __align__(1024) __half g_h [(size_t)M_NODES * HID_DIM];

__device__ __forceinline__ uint32_t sw128(uint32_t off) { return off ^ ((off >> 3) & 0x70); }

__device__ __forceinline__ uint32_t h2u(__half2 h) {
    __half2_raw r = *reinterpret_cast<__half2_raw*>(&h);
    return (uint32_t)r.x | ((uint32_t)r.y << 16);
}

// ---------------------------------------------------------------------------
// Conversion: fp32 row-major -> fp16 tiled+swizzled (granule = 16B = 8 halves)
// ---------------------------------------------------------------------------
__global__ void cvt_tiled(const float* __restrict__ src0, const int* __restrict__ idx,
                          size_t per_expert, __half* __restrict__ dst,
                          int K, int KT, size_t n_gran) {
    size_t g = (size_t)blockIdx.x * blockDim.x + threadIdx.x;
    if (g >= n_gran) return;
    const float* src = idx ? (src0 + (size_t)(*idx) * per_expert) : src0;
    uint32_t t  = (uint32_t)(g >> 10);
    uint32_t gi = (uint32_t)(g & 1023);
    uint32_t r  = gi >> 3, q = gi & 7;
    uint32_t rb = t / KT, c = t % KT;
    const float4* s = reinterpret_cast<const float4*>(
        src + ((size_t)rb * 128 + r) * K + (size_t)c * 64 + q * 8);
    float4 v0 = s[0], v1 = s[1];
    uint4 pack;
    pack.x = h2u(__floats2half2_rn(v0.x, v0.y));
    pack.y = h2u(__floats2half2_rn(v0.z, v0.w));
    pack.z = h2u(__floats2half2_rn(v1.x, v1.y));
    pack.w = h2u(__floats2half2_rn(v1.z, v1.w));
    uint32_t off = sw128(r * 128 + q * 16);
    *reinterpret_cast<uint4*>(reinterpret_cast<char*>(dst) + (size_t)t * TILE_BYTES + off) = pack;
}

// ---------------------------------------------------------------------------
// PTX wrappers
// ---------------------------------------------------------------------------
__device__ __forceinline__ void cp_async16(uint32_t saddr, const void* gaddr) {
    asm volatile("cp.async.cg.shared.global [%0], [%1], 16;\n" :: "r"(saddr), "l"(gaddr));
}
__device__ __forceinline__ void cp_commit() {
    asm volatile("cp.async.commit_group;\n");
}
template<int N>
__device__ __forceinline__ void cp_wait() {
    asm volatile("cp.async.wait_group %0;\n" :: "n"(N));
}
__device__ __forceinline__ void ldmatrix_x4(uint32_t& r0, uint32_t& r1,
                                            uint32_t& r2, uint32_t& r3, uint32_t addr) {
    asm volatile("ldmatrix.sync.aligned.m8n8.x4.shared.b16 {%0,%1,%2,%3}, [%4];"
                 : "=r"(r0), "=r"(r1), "=r"(r2), "=r"(r3) : "r"(addr));
}
__device__ __forceinline__ void mma_16816(float& d0, float& d1, float& d2, float& d3,
                                          uint32_t a0, uint32_t a1, uint32_t a2, uint32_t a3,
                                          uint32_t b0, uint32_t b1) {
    asm volatile("mma.sync.aligned.m16n8k16.row.col.f32.f16.f16.f32 "
                 "{%0,%1,%2,%3}, {%4,%5,%6,%7}, {%8,%9}, {%0,%1,%2,%3};"
                 : "+f"(d0), "+f"(d1), "+f"(d2), "+f"(d3)
                 : "r"(a0), "r"(a1), "r"(a2), "r"(a3), "r"(b0), "r"(b1));
}
__device__ __forceinline__ float gelu_erf(float v) {
    return 0.5f * v * (1.0f + erff(v * 0.70710678118654752f));
}

// ---------------------------------------------------------------------------
// GEMM: C[128x256 tile] = A[128,K] * B[256,K]^T, fp16 in / fp32 accum.
// A,B in tiled+swizzled gmem. 8 warps, warp tile 64x64, 1 CTA/SM, 4-stage pipe.
// A fragments double-buffered across kk; B fragments single-buffered (reg cap).
// ---------------------------------------------------------------------------
template<bool GELU>
__global__ __launch_bounds__(256, 1)
void hmma_gemm(const char* __restrict__ gA, const char* __restrict__ gB,
               void* __restrict__ out, int KT, int KT_DST)
{
    extern __shared__ __align__(128) char smem[];
    const uint32_t sbase = (uint32_t)__cvta_generic_to_shared(smem);

    const int tid  = threadIdx.x;
    const int warp = tid >> 5;
    const int lane = tid & 31;
    const int wm   = warp & 1;             // 0..1 : 64-row slab
    const int wn   = warp >> 1;            // 0..3 : 64-col slab
    const int bm   = blockIdx.y * 128;
    const int bn   = blockIdx.x * 256;

    const char* baseA  = gA + (size_t)blockIdx.y * KT * TILE_BYTES;
    const char* baseB0 = gB + (size_t)(blockIdx.x * 2) * KT * TILE_BYTES;
    const char* baseB1 = baseB0 + (size_t)KT * TILE_BYTES;

    float acc[4][8][4];
    #pragma unroll
    for (int i = 0; i < 4; i++)
        #pragma unroll
        for (int j = 0; j < 8; j++)
            #pragma unroll
            for (int r = 0; r < 4; r++) acc[i][j][r] = 0.0f;

    // ---- linear stage loader: 3072 granules of 16B, 12 per thread ----
    auto load_stage = [&](int kt, int s) {
        const uint32_t st = sbase + (uint32_t)s * STAGE_BYTES;
        const char* sA  = baseA  + (size_t)kt * TILE_BYTES;
        const char* sB0 = baseB0 + (size_t)kt * TILE_BYTES;
        const char* sB1 = baseB1 + (size_t)kt * TILE_BYTES;
        #pragma unroll
        for (int i = 0; i < 4; i++) {
            uint32_t o = (uint32_t)(tid + i * 256) * 16;
            cp_async16(st + o, sA + o);
        }
        #pragma unroll
        for (int i = 0; i < 4; i++) {
            uint32_t o = (uint32_t)(tid + i * 256) * 16;
            cp_async16(st + TILE_BYTES + o, sB0 + o);
        }
        #pragma unroll
        for (int i = 0; i < 4; i++) {
            uint32_t o = (uint32_t)(tid + i * 256) * 16;
            cp_async16(st + 2 * TILE_BYTES + o, sB1 + o);
        }
        cp_commit();
    };

    // ---- precomputed ldmatrix base offsets (per-kk addr = base ^ kk*32) ----
    const uint32_t fc2 = (uint32_t)(lane >> 4) * 16;
    uint32_t rowA[4], rowB[4];
    #pragma unroll
    for (int mi = 0; mi < 4; mi++) {
        uint32_t r = wm * 64 + mi * 16 + (lane & 15);
        rowA[mi] = r * 128 + (fc2 ^ ((r & 7) << 4));
    }
    #pragma unroll
    for (int p = 0; p < 4; p++) {
        uint32_t r = wn * 64 + p * 16 + (lane & 15);
        rowB[p] = r * 128 + (fc2 ^ ((r & 7) << 4));
    }

    uint32_t af[2][4][4];   // A: double-buffered across kk
    uint32_t bf[4][4];      // B: single-buffered (register budget)

    // ---- prologue: fill 3 stages ----
    load_stage(0, 0);
    if (KT > 1) load_stage(1, 1);
    if (KT > 2) load_stage(2, 2);

    int slot = 0, slot_next = 3 % NSTAGE;
    for (int kt = 0; kt < KT; kt++) {
        if (kt + 2 < KT) cp_wait<2>();
        else if (kt + 1 < KT) cp_wait<1>();
        else cp_wait<0>();
        __syncthreads();
        if (kt + 3 < KT) {
            load_stage(kt + 3, slot_next);
            slot_next = (slot_next + 1) & (NSTAGE - 1);
        }

        const uint32_t sa  = sbase + (uint32_t)slot * STAGE_BYTES;
        const uint32_t sbB = sa + TILE_BYTES;
        slot = (slot + 1) & (NSTAGE - 1);

        // A prefetch for kk=0
        #pragma unroll
        for (int mi = 0; mi < 4; mi++)
            ldmatrix_x4(af[0][mi][0], af[0][mi][1], af[0][mi][2], af[0][mi][3],
                        sa + rowA[mi]);

        #pragma unroll
        for (int kk = 0; kk < 4; kk++) {
            const uint32_t kx = (uint32_t)kk * 32;
            // B for this kk (single buffer)
            #pragma unroll
            for (int p = 0; p < 4; p++)
                ldmatrix_x4(bf[p][0], bf[p][1], bf[p][2], bf[p][3],
                            sbB + (rowB[p] ^ kx));
            // A prefetch for kk+1
            if (kk < 3) {
                const uint32_t kx1 = (uint32_t)(kk + 1) * 32;
                #pragma unroll
                for (int mi = 0; mi < 4; mi++)
                    ldmatrix_x4(af[(kk + 1) & 1][mi][0], af[(kk + 1) & 1][mi][1],
                                af[(kk + 1) & 1][mi][2], af[(kk + 1) & 1][mi][3],
                                sa + (rowA[mi] ^ kx1));
            }
            const int b = kk & 1;
            #pragma unroll
            for (int mi = 0; mi < 4; mi++) {
                #pragma unroll
                for (int p = 0; p < 4; p++) {
                    mma_16816(acc[mi][2*p][0], acc[mi][2*p][1], acc[mi][2*p][2], acc[mi][2*p][3],
                              af[b][mi][0], af[b][mi][1], af[b][mi][2], af[b][mi][3],
                              bf[p][0], bf[p][2]);
                    mma_16816(acc[mi][2*p+1][0], acc[mi][2*p+1][1], acc[mi][2*p+1][2], acc[mi][2*p+1][3],
                              af[b][mi][0], af[b][mi][1], af[b][mi][2], af[b][mi][3],
                              bf[p][1], bf[p][3]);
                }
            }
        }
    }

    // ---- epilogue ----
    const int qrow = lane >> 2;            // 0..7
    const int qcol = (lane & 3) * 2;       // 0,2,4,6
    #pragma unroll
    for (int mi = 0; mi < 4; mi++) {
        #pragma unroll
        for (int ni = 0; ni < 8; ni++) {
            float c0 = acc[mi][ni][0], c1 = acc[mi][ni][1];
            float c2 = acc[mi][ni][2], c3 = acc[mi][ni][3];
            int lrow = wm * 64 + mi * 16 + qrow;           // local row in 128-tile
            int col  = bn + wn * 64 + ni * 8 + qcol;       // global col
            if (GELU) {
                size_t tb = ((size_t)(bm >> 7) * KT_DST + (uint32_t)(col >> 6)) * TILE_BYTES;
                char* dst = (char*)out + tb;
                uint32_t cb = (uint32_t)(col & 63) * 2;
                __half2 v01 = __floats2half2_rn(gelu_erf(c0), gelu_erf(c1));
                __half2 v23 = __floats2half2_rn(gelu_erf(c2), gelu_erf(c3));
                *reinterpret_cast<__half2*>(dst + sw128((uint32_t)lrow * 128 + cb))       = v01;
                *reinterpret_cast<__half2*>(dst + sw128((uint32_t)(lrow + 8) * 128 + cb)) = v23;
            } else {
                float* o = (float*)out;
                size_t r0 = (size_t)(bm + lrow) * OUT_DIM + col;
                *reinterpret_cast<float2*>(o + r0)                       = make_float2(c0, c1);
                *reinterpret_cast<float2*>(o + r0 + (size_t)8 * OUT_DIM) = make_float2(c2, c3);
            }
        }
    }
}

// ---------------------------------------------------------------------------
// launch
// ---------------------------------------------------------------------------
extern "C" void kernel_launch(void* const* d_in, const int* in_sizes, int n_in,
                              void* d_out, int out_size) {
    const int*   d_idx = (const int*)  d_in[0];
    const float* d_x   = (const float*)d_in[1];
    const float* d_W1  = (const float*)d_in[2];
    const float* d_W2  = (const float*)d_in[3];

    __half *px, *pw1, *pw2, *ph;
    cudaGetSymbolAddress((void**)&px,  g_x);
    cudaGetSymbolAddress((void**)&pw1, g_w1);
    cudaGetSymbolAddress((void**)&pw2, g_w2);
    cudaGetSymbolAddress((void**)&ph,  g_h);

    cudaFuncSetAttribute(hmma_gemm<true>,  cudaFuncAttributeMaxDynamicSharedMemorySize, SMEM_BYTES);
    cudaFuncSetAttribute(hmma_gemm<false>, cudaFuncAttributeMaxDynamicSharedMemorySize, SMEM_BYTES);

    // 1) x -> tiled fp16 (KT=32)
    {
        size_t ng = (size_t)M_NODES * IN_DIM / 8;
        cvt_tiled<<<(unsigned)((ng + 255) / 256), 256>>>(d_x, nullptr, 0, px, IN_DIM, IN_DIM / 64, ng);
    }
    // 2) W1[e] -> tiled fp16 (KT=32)
    {
        size_t pe = (size_t)HID_DIM * IN_DIM;
        size_t ng = pe / 8;
        cvt_tiled<<<(unsigned)((ng + 255) / 256), 256>>>(d_W1, d_idx, pe, pw1, IN_DIM, IN_DIM / 64, ng);
    }
    // 3) W2[e] -> tiled fp16 (KT=64)
    {
        size_t pe = (size_t)OUT_DIM * HID_DIM;
        size_t ng = pe / 8;
        cvt_tiled<<<(unsigned)((ng + 255) / 256), 256>>>(d_W2, d_idx, pe, pw2, HID_DIM, HID_DIM / 64, ng);
    }
    // 4) h = gelu(x @ W1^T) -> tiled fp16, dst KT=64
    {
        dim3 grid(HID_DIM / 256, M_NODES / 128);
        hmma_gemm<true><<<grid, 256, SMEM_BYTES>>>((const char*)px, (const char*)pw1, ph,
                                                   IN_DIM / 64, HID_DIM / 64);
    }
    // 5) out = h @ W2^T -> fp32 row-major
    {
        dim3 grid(OUT_DIM / 256, M_NODES / 128);
        hmma_gemm<false><<<grid, 256, SMEM_BYTES>>>((const char*)ph, (const char*)pw2, d_out,
                                                    HID_DIM / 64, 0);
    }
}

// round 16
// speedup vs baseline: 1.1787x; 1.0846x over previous
#include <cuda_runtime.h>
#include <cuda_fp16.h>
#include <cstdint>
#include <math.h>

#define M_NODES 16384
#define IN_DIM  2048
#define HID_DIM 4096
#define OUT_DIM 2048

#define TILE_BYTES 16384          // 128 rows x 64 halves (128B), SW128-swizzled
#define NSTAGE 3
#define STAGE_BYTES (2 * TILE_BYTES)   // A tile + B tile
#define SMEM_BYTES  (NSTAGE * STAGE_BYTES)   // 96 KB -> 2 CTA/SM

// ---------------------------------------------------------------------------
// fp16 scratch, tiled+swizzled layout (static device arrays -- no allocation)
// tile t = row_block*KT + k_chunk; byte(r,h) at t*16384 + SW128(r*128 + h*2)
// ---------------------------------------------------------------------------
__device__ __align__(1024) __half g_x [(size_t)M_NODES * IN_DIM];
__device__ __align__(1024) __half g_w1[(size_t)HID_DIM * IN_DIM];
__device__ __align__(1024) __half g_w2[(size_t)OUT_DIM * HID_DIM];
__device__ __align__(1024) __half g_h [(size_t)M_NODES * HID_DIM];

__device__ __forceinline__ uint32_t sw128(uint32_t off) { return off ^ ((off >> 3) & 0x70); }

__device__ __forceinline__ uint32_t h2u(__half2 h) {
    __half2_raw r = *reinterpret_cast<__half2_raw*>(&h);
    return (uint32_t)r.x | ((uint32_t)r.y << 16);
}

// ---------------------------------------------------------------------------
// Conversion: fp32 row-major -> fp16 tiled+swizzled (granule = 16B = 8 halves)
// ---------------------------------------------------------------------------
__global__ void cvt_tiled(const float* __restrict__ src0, const int* __restrict__ idx,
                          size_t per_expert, __half* __restrict__ dst,
                          int K, int KT, size_t n_gran) {
    size_t g = (size_t)blockIdx.x * blockDim.x + threadIdx.x;
    if (g >= n_gran) return;
    const float* src = idx ? (src0 + (size_t)(*idx) * per_expert) : src0;
    uint32_t t  = (uint32_t)(g >> 10);
    uint32_t gi = (uint32_t)(g & 1023);
    uint32_t r  = gi >> 3, q = gi & 7;
    uint32_t rb = t / KT, c = t % KT;
    const float4* s = reinterpret_cast<const float4*>(
        src + ((size_t)rb * 128 + r) * K + (size_t)c * 64 + q * 8);
    float4 v0 = s[0], v1 = s[1];
    uint4 pack;
    pack.x = h2u(__floats2half2_rn(v0.x, v0.y));
    pack.y = h2u(__floats2half2_rn(v0.z, v0.w));
    pack.z = h2u(__floats2half2_rn(v1.x, v1.y));
    pack.w = h2u(__floats2half2_rn(v1.z, v1.w));
    uint32_t off = sw128(r * 128 + q * 16);
    *reinterpret_cast<uint4*>(reinterpret_cast<char*>(dst) + (size_t)t * TILE_BYTES + off) = pack;
}

// ---------------------------------------------------------------------------
// PTX wrappers
// ---------------------------------------------------------------------------
__device__ __forceinline__ void cp_async16(uint32_t saddr, const void* gaddr) {
    asm volatile("cp.async.cg.shared.global [%0], [%1], 16;\n" :: "r"(saddr), "l"(gaddr));
}
__device__ __forceinline__ void cp_commit() {
    asm volatile("cp.async.commit_group;\n");
}
template<int N>
__device__ __forceinline__ void cp_wait() {
    asm volatile("cp.async.wait_group %0;\n" :: "n"(N));
}
__device__ __forceinline__ void ldmatrix_x4(uint32_t& r0, uint32_t& r1,
                                            uint32_t& r2, uint32_t& r3, uint32_t addr) {
    asm volatile("ldmatrix.sync.aligned.m8n8.x4.shared.b16 {%0,%1,%2,%3}, [%4];"
                 : "=r"(r0), "=r"(r1), "=r"(r2), "=r"(r3) : "r"(addr));
}
__device__ __forceinline__ void mma_16816(float& d0, float& d1, float& d2, float& d3,
                                          uint32_t a0, uint32_t a1, uint32_t a2, uint32_t a3,
                                          uint32_t b0, uint32_t b1) {
    asm volatile("mma.sync.aligned.m16n8k16.row.col.f32.f16.f16.f32 "
                 "{%0,%1,%2,%3}, {%4,%5,%6,%7}, {%8,%9}, {%0,%1,%2,%3};"
                 : "+f"(d0), "+f"(d1), "+f"(d2), "+f"(d3)
                 : "r"(a0), "r"(a1), "r"(a2), "r"(a3), "r"(b0), "r"(b1));
}
__device__ __forceinline__ float gelu_erf(float v) {
    return 0.5f * v * (1.0f + erff(v * 0.70710678118654752f));
}

// ---------------------------------------------------------------------------
// GEMM: C[128x128 tile] = A[128,K] * B[128,K]^T, fp16 in / fp32 accum.
// A,B in tiled+swizzled gmem. 8 warps, warp tile 64x32, 2 CTA/SM, 3-stage pipe.
// KT is compile-time: full strength reduction of slot/offset arithmetic.
// ---------------------------------------------------------------------------
template<bool GELU, int KT, int KT_DST>
__global__ __launch_bounds__(256, 2)
void hmma_gemm(const char* __restrict__ gA, const char* __restrict__ gB,
               void* __restrict__ out)
{
    extern __shared__ __align__(128) char smem[];
    const uint32_t sbase = (uint32_t)__cvta_generic_to_shared(smem);

    const int tid  = threadIdx.x;
    const int warp = tid >> 5;
    const int lane = tid & 31;
    const int wm   = warp >> 2;            // 0..1 : 64-row slab
    const int wn   = warp & 3;             // 0..3 : 32-col slab
    const int bm   = blockIdx.y * 128;
    const int bn   = blockIdx.x * 128;

    const char* baseA = gA + (size_t)blockIdx.y * KT * TILE_BYTES;
    const char* baseB = gB + (size_t)blockIdx.x * KT * TILE_BYTES;

    float acc[4][4][4];
    #pragma unroll
    for (int i = 0; i < 4; i++)
        #pragma unroll
        for (int j = 0; j < 4; j++)
            #pragma unroll
            for (int r = 0; r < 4; r++) acc[i][j][r] = 0.0f;

    // ---- linear stage loader: 2048 granules of 16B, 8 per thread ----
    auto load_stage = [&](int kt, int s) {
        const uint32_t st = sbase + (uint32_t)s * STAGE_BYTES;
        const char* sA = baseA + (size_t)kt * TILE_BYTES;
        const char* sB = baseB + (size_t)kt * TILE_BYTES;
        #pragma unroll
        for (int i = 0; i < 4; i++) {
            uint32_t o = (uint32_t)(tid + i * 256) * 16;
            cp_async16(st + o, sA + o);
        }
        #pragma unroll
        for (int i = 0; i < 4; i++) {
            uint32_t o = (uint32_t)(tid + i * 256) * 16;
            cp_async16(st + TILE_BYTES + o, sB + o);
        }
        cp_commit();
    };

    // ---- precomputed ldmatrix base offsets (per-kk addr = base ^ kk*32) ----
    const uint32_t fc2 = (uint32_t)(lane >> 4) * 16;
    uint32_t rowA[4], rowB[2];
    #pragma unroll
    for (int mi = 0; mi < 4; mi++) {
        uint32_t r = wm * 64 + mi * 16 + (lane & 15);
        rowA[mi] = r * 128 + (fc2 ^ ((r & 7) << 4));
    }
    #pragma unroll
    for (int p = 0; p < 2; p++) {
        uint32_t r = wn * 32 + p * 16 + (lane & 15);
        rowB[p] = r * 128 + (fc2 ^ ((r & 7) << 4));
    }

    uint32_t af[2][4][4];
    uint32_t bf[2][2][4];

    load_stage(0, 0);
    load_stage(1, 1);

    #pragma unroll 1
    for (int kt = 0; kt < KT; kt++) {
        if (kt + 1 < KT) cp_wait<1>(); else cp_wait<0>();
        __syncthreads();

        const int slot = kt % NSTAGE;
        const uint32_t sa  = sbase + (uint32_t)slot * STAGE_BYTES;
        const uint32_t sbB = sa + TILE_BYTES;

        // kk=0 fragments FIRST (restart tensor pipe asap), then next-stage loads
        auto ldf = [&](int kk, int b) {
            const uint32_t kx = (uint32_t)kk * 32;
            #pragma unroll
            for (int mi = 0; mi < 4; mi++)
                ldmatrix_x4(af[b][mi][0], af[b][mi][1], af[b][mi][2], af[b][mi][3],
                            sa + (rowA[mi] ^ kx));
            #pragma unroll
            for (int p = 0; p < 2; p++)
                ldmatrix_x4(bf[b][p][0], bf[b][p][1], bf[b][p][2], bf[b][p][3],
                            sbB + (rowB[p] ^ kx));
        };

        ldf(0, 0);
        if (kt + 2 < KT) load_stage(kt + 2, (kt + 2) % NSTAGE);

        #pragma unroll
        for (int kk = 0; kk < 4; kk++) {
            if (kk < 3) ldf(kk + 1, (kk + 1) & 1);
            const int b = kk & 1;
            #pragma unroll
            for (int mi = 0; mi < 4; mi++) {
                #pragma unroll
                for (int p = 0; p < 2; p++) {
                    mma_16816(acc[mi][2*p][0], acc[mi][2*p][1], acc[mi][2*p][2], acc[mi][2*p][3],
                              af[b][mi][0], af[b][mi][1], af[b][mi][2], af[b][mi][3],
                              bf[b][p][0], bf[b][p][2]);
                    mma_16816(acc[mi][2*p+1][0], acc[mi][2*p+1][1], acc[mi][2*p+1][2], acc[mi][2*p+1][3],
                              af[b][mi][0], af[b][mi][1], af[b][mi][2], af[b][mi][3],
                              bf[b][p][1], bf[b][p][3]);
                }
            }
        }
    }

    // ---- epilogue ----
    const int qrow = lane >> 2;            // 0..7
    const int qcol = (lane & 3) * 2;       // 0,2,4,6
    #pragma unroll
    for (int mi = 0; mi < 4; mi++) {
        #pragma unroll
        for (int ni = 0; ni < 4; ni++) {
            float c0 = acc[mi][ni][0], c1 = acc[mi][ni][1];
            float c2 = acc[mi][ni][2], c3 = acc[mi][ni][3];
            int lrow = wm * 64 + mi * 16 + qrow;           // local row in 128-tile
            int col  = bn + wn * 32 + ni * 8 + qcol;       // global col
            if (GELU) {
                size_t tb = ((size_t)(bm >> 7) * KT_DST + (uint32_t)(col >> 6)) * TILE_BYTES;
                char* dst = (char*)out + tb;
                uint32_t cb = (uint32_t)(col & 63) * 2;
                __half2 v01 = __floats2half2_rn(gelu_erf(c0), gelu_erf(c1));
                __half2 v23 = __floats2half2_rn(gelu_erf(c2), gelu_erf(c3));
                *reinterpret_cast<__half2*>(dst + sw128((uint32_t)lrow * 128 + cb))       = v01;
                *reinterpret_cast<__half2*>(dst + sw128((uint32_t)(lrow + 8) * 128 + cb)) = v23;
            } else {
                float* o = (float*)out;
                size_t r0 = (size_t)(bm + lrow) * OUT_DIM + col;
                *reinterpret_cast<float2*>(o + r0)                       = make_float2(c0, c1);
                *reinterpret_cast<float2*>(o + r0 + (size_t)8 * OUT_DIM) = make_float2(c2, c3);
            }
        }
    }
}

// ---------------------------------------------------------------------------
// launch
// ---------------------------------------------------------------------------
extern "C" void kernel_launch(void* const* d_in, const int* in_sizes, int n_in,
                              void* d_out, int out_size) {
    const int*   d_idx = (const int*)  d_in[0];
    const float* d_x   = (const float*)d_in[1];
    const float* d_W1  = (const float*)d_in[2];
    const float* d_W2  = (const float*)d_in[3];

    __half *px, *pw1, *pw2, *ph;
    cudaGetSymbolAddress((void**)&px,  g_x);
    cudaGetSymbolAddress((void**)&pw1, g_w1);
    cudaGetSymbolAddress((void**)&pw2, g_w2);
    cudaGetSymbolAddress((void**)&ph,  g_h);

    cudaFuncSetAttribute((const void*)hmma_gemm<true, 32, 64>,
                         cudaFuncAttributeMaxDynamicSharedMemorySize, SMEM_BYTES);
    cudaFuncSetAttribute((const void*)hmma_gemm<false, 64, 0>,
                         cudaFuncAttributeMaxDynamicSharedMemorySize, SMEM_BYTES);

    // 1) x -> tiled fp16 (KT=32)
    {
        size_t ng = (size_t)M_NODES * IN_DIM / 8;
        cvt_tiled<<<(unsigned)((ng + 255) / 256), 256>>>(d_x, nullptr, 0, px, IN_DIM, IN_DIM / 64, ng);
    }
    // 2) W1[e] -> tiled fp16 (KT=32)
    {
        size_t pe = (size_t)HID_DIM * IN_DIM;
        size_t ng = pe / 8;
        cvt_tiled<<<(unsigned)((ng + 255) / 256), 256>>>(d_W1, d_idx, pe, pw1, IN_DIM, IN_DIM / 64, ng);
    }
    // 3) W2[e] -> tiled fp16 (KT=64)
    {
        size_t pe = (size_t)OUT_DIM * HID_DIM;
        size_t ng = pe / 8;
        cvt_tiled<<<(unsigned)((ng + 255) / 256), 256>>>(d_W2, d_idx, pe, pw2, HID_DIM, HID_DIM / 64, ng);
    }
    // 4) h = gelu(x @ W1^T) -> tiled fp16, dst KT=64
    {
        dim3 grid(HID_DIM / 128, M_NODES / 128);
        hmma_gemm<true, 32, 64><<<grid, 256, SMEM_BYTES>>>((const char*)px, (const char*)pw1, ph);
    }
    // 5) out = h @ W2^T -> fp32 row-major
    {
        dim3 grid(OUT_DIM / 128, M_NODES / 128);
        hmma_gemm<false, 64, 0><<<grid, 256, SMEM_BYTES>>>((const char*)ph, (const char*)pw2, d_out);
    }
}

// round 17
// speedup vs baseline: 1.2032x; 1.0208x over previous
#include <cuda_runtime.h>
#include <cuda_fp16.h>
#include <cstdint>
#include <math.h>

#define M_NODES 16384
#define IN_DIM  2048
#define HID_DIM 4096
#define OUT_DIM 2048

#define TILE_BYTES 16384          // 128 rows x 64 halves (128B), SW128-swizzled
#define NSTAGE 3
#define STAGE_BYTES (2 * TILE_BYTES)   // A tile + B tile
#define SMEM_BYTES  (NSTAGE * STAGE_BYTES)   // 96 KB -> 2 CTA/SM

// ---------------------------------------------------------------------------
// fp16 scratch, tiled+swizzled layout (static device arrays -- no allocation)
// tile t = row_block*KT + k_chunk; byte(r,h) at t*16384 + SW128(r*128 + h*2)
// ---------------------------------------------------------------------------
__device__ __align__(1024) __half g_x [(size_t)M_NODES * IN_DIM];
__device__ __align__(1024) __half g_w1[(size_t)HID_DIM * IN_DIM];
__device__ __align__(1024) __half g_w2[(size_t)OUT_DIM * HID_DIM];
__device__ __align__(1024) __half g_h [(size_t)M_NODES * HID_DIM];

__device__ __forceinline__ uint32_t sw128(uint32_t off) { return off ^ ((off >> 3) & 0x70); }

__device__ __forceinline__ uint32_t h2u(__half2 h) {
    __half2_raw r = *reinterpret_cast<__half2_raw*>(&h);
    return (uint32_t)r.x | ((uint32_t)r.y << 16);
}

// ---------------------------------------------------------------------------
// Conversion: fp32 row-major -> fp16 tiled+swizzled (granule = 16B = 8 halves)
// ---------------------------------------------------------------------------
__global__ void cvt_tiled(const float* __restrict__ src0, const int* __restrict__ idx,
                          size_t per_expert, __half* __restrict__ dst,
                          int K, int KT, size_t n_gran) {
    size_t g = (size_t)blockIdx.x * blockDim.x + threadIdx.x;
    if (g >= n_gran) return;
    const float* src = idx ? (src0 + (size_t)(*idx) * per_expert) : src0;
    uint32_t t  = (uint32_t)(g >> 10);
    uint32_t gi = (uint32_t)(g & 1023);
    uint32_t r  = gi >> 3, q = gi & 7;
    uint32_t rb = t / KT, c = t % KT;
    const float4* s = reinterpret_cast<const float4*>(
        src + ((size_t)rb * 128 + r) * K + (size_t)c * 64 + q * 8);
    float4 v0 = s[0], v1 = s[1];
    uint4 pack;
    pack.x = h2u(__floats2half2_rn(v0.x, v0.y));
    pack.y = h2u(__floats2half2_rn(v0.z, v0.w));
    pack.z = h2u(__floats2half2_rn(v1.x, v1.y));
    pack.w = h2u(__floats2half2_rn(v1.z, v1.w));
    uint32_t off = sw128(r * 128 + q * 16);
    *reinterpret_cast<uint4*>(reinterpret_cast<char*>(dst) + (size_t)t * TILE_BYTES + off) = pack;
}

// ---------------------------------------------------------------------------
// PTX wrappers
// ---------------------------------------------------------------------------
__device__ __forceinline__ void cp_async16(uint32_t saddr, const void* gaddr) {
    asm volatile("cp.async.cg.shared.global [%0], [%1], 16;\n" :: "r"(saddr), "l"(gaddr));
}
__device__ __forceinline__ void cp_commit() {
    asm volatile("cp.async.commit_group;\n");
}
template<int N>
__device__ __forceinline__ void cp_wait() {
    asm volatile("cp.async.wait_group %0;\n" :: "n"(N));
}
__device__ __forceinline__ void ldmatrix_x4(uint32_t& r0, uint32_t& r1,
                                            uint32_t& r2, uint32_t& r3, uint32_t addr) {
    asm volatile("ldmatrix.sync.aligned.m8n8.x4.shared.b16 {%0,%1,%2,%3}, [%4];"
                 : "=r"(r0), "=r"(r1), "=r"(r2), "=r"(r3) : "r"(addr));
}
__device__ __forceinline__ void mma_16816(float& d0, float& d1, float& d2, float& d3,
                                          uint32_t a0, uint32_t a1, uint32_t a2, uint32_t a3,
                                          uint32_t b0, uint32_t b1) {
    asm volatile("mma.sync.aligned.m16n8k16.row.col.f32.f16.f16.f32 "
                 "{%0,%1,%2,%3}, {%4,%5,%6,%7}, {%8,%9}, {%0,%1,%2,%3};"
                 : "+f"(d0), "+f"(d1), "+f"(d2), "+f"(d3)
                 : "r"(a0), "r"(a1), "r"(a2), "r"(a3), "r"(b0), "r"(b1));
}
__device__ __forceinline__ float gelu_erf(float v) {
    return 0.5f * v * (1.0f + erff(v * 0.70710678118654752f));
}

// ---------------------------------------------------------------------------
// GEMM: C[128x128 tile] = A[128,K] * B[128,K]^T, fp16 in / fp32 accum.
// A,B in tiled+swizzled gmem. 8 warps, warp tile 64x32, 2 CTA/SM, 3-stage pipe.
// Fragments SINGLE-buffered: low reg pressure; latency hidden across 16 warps/SM.
// ---------------------------------------------------------------------------
template<bool GELU, int KT, int KT_DST>
__global__ __launch_bounds__(256, 2)
void hmma_gemm(const char* __restrict__ gA, const char* __restrict__ gB,
               void* __restrict__ out)
{
    extern __shared__ __align__(128) char smem[];
    const uint32_t sbase = (uint32_t)__cvta_generic_to_shared(smem);

    const int tid  = threadIdx.x;
    const int warp = tid >> 5;
    const int lane = tid & 31;
    const int wm   = warp >> 2;            // 0..1 : 64-row slab
    const int wn   = warp & 3;             // 0..3 : 32-col slab
    const int bm   = blockIdx.y * 128;
    const int bn   = blockIdx.x * 128;

    const char* baseA = gA + (size_t)blockIdx.y * KT * TILE_BYTES;
    const char* baseB = gB + (size_t)blockIdx.x * KT * TILE_BYTES;

    float acc[4][4][4];
    #pragma unroll
    for (int i = 0; i < 4; i++)
        #pragma unroll
        for (int j = 0; j < 4; j++)
            #pragma unroll
            for (int r = 0; r < 4; r++) acc[i][j][r] = 0.0f;

    // ---- linear stage loader: 2048 granules of 16B, 8 per thread ----
    auto load_stage = [&](int kt, int s) {
        const uint32_t st = sbase + (uint32_t)s * STAGE_BYTES;
        const char* sA = baseA + (size_t)kt * TILE_BYTES;
        const char* sB = baseB + (size_t)kt * TILE_BYTES;
        #pragma unroll
        for (int i = 0; i < 4; i++) {
            uint32_t o = (uint32_t)(tid + i * 256) * 16;
            cp_async16(st + o, sA + o);
        }
        #pragma unroll
        for (int i = 0; i < 4; i++) {
            uint32_t o = (uint32_t)(tid + i * 256) * 16;
            cp_async16(st + TILE_BYTES + o, sB + o);
        }
        cp_commit();
    };

    // ---- precomputed ldmatrix base offsets (per-kk addr = base ^ kk*32) ----
    const uint32_t fc2 = (uint32_t)(lane >> 4) * 16;
    uint32_t rowA[4], rowB[2];
    #pragma unroll
    for (int mi = 0; mi < 4; mi++) {
        uint32_t r = wm * 64 + mi * 16 + (lane & 15);
        rowA[mi] = r * 128 + (fc2 ^ ((r & 7) << 4));
    }
    #pragma unroll
    for (int p = 0; p < 2; p++) {
        uint32_t r = wn * 32 + p * 16 + (lane & 15);
        rowB[p] = r * 128 + (fc2 ^ ((r & 7) << 4));
    }

    uint32_t af[4][4];    // single-buffered A fragments
    uint32_t bf[2][4];    // single-buffered B fragments

    load_stage(0, 0);
    load_stage(1, 1);

    #pragma unroll 1
    for (int kt = 0; kt < KT; kt++) {
        if (kt + 1 < KT) cp_wait<1>(); else cp_wait<0>();
        __syncthreads();

        const int slot = kt % NSTAGE;
        const uint32_t sa  = sbase + (uint32_t)slot * STAGE_BYTES;
        const uint32_t sbB = sa + TILE_BYTES;

        if (kt + 2 < KT) load_stage(kt + 2, (kt + 2) % NSTAGE);

        #pragma unroll
        for (int kk = 0; kk < 4; kk++) {
            const uint32_t kx = (uint32_t)kk * 32;
            #pragma unroll
            for (int mi = 0; mi < 4; mi++)
                ldmatrix_x4(af[mi][0], af[mi][1], af[mi][2], af[mi][3],
                            sa + (rowA[mi] ^ kx));
            #pragma unroll
            for (int p = 0; p < 2; p++)
                ldmatrix_x4(bf[p][0], bf[p][1], bf[p][2], bf[p][3],
                            sbB + (rowB[p] ^ kx));
            #pragma unroll
            for (int mi = 0; mi < 4; mi++) {
                #pragma unroll
                for (int p = 0; p < 2; p++) {
                    mma_16816(acc[mi][2*p][0], acc[mi][2*p][1], acc[mi][2*p][2], acc[mi][2*p][3],
                              af[mi][0], af[mi][1], af[mi][2], af[mi][3],
                              bf[p][0], bf[p][2]);
                    mma_16816(acc[mi][2*p+1][0], acc[mi][2*p+1][1], acc[mi][2*p+1][2], acc[mi][2*p+1][3],
                              af[mi][0], af[mi][1], af[mi][2], af[mi][3],
                              bf[p][1], bf[p][3]);
                }
            }
        }
    }

    // ---- epilogue ----
    const int qrow = lane >> 2;            // 0..7
    const int qcol = (lane & 3) * 2;       // 0,2,4,6
    #pragma unroll
    for (int mi = 0; mi < 4; mi++) {
        #pragma unroll
        for (int ni = 0; ni < 4; ni++) {
            float c0 = acc[mi][ni][0], c1 = acc[mi][ni][1];
            float c2 = acc[mi][ni][2], c3 = acc[mi][ni][3];
            int lrow = wm * 64 + mi * 16 + qrow;           // local row in 128-tile
            int col  = bn + wn * 32 + ni * 8 + qcol;       // global col
            if (GELU) {
                size_t tb = ((size_t)(bm >> 7) * KT_DST + (uint32_t)(col >> 6)) * TILE_BYTES;
                char* dst = (char*)out + tb;
                uint32_t cb = (uint32_t)(col & 63) * 2;
                __half2 v01 = __floats2half2_rn(gelu_erf(c0), gelu_erf(c1));
                __half2 v23 = __floats2half2_rn(gelu_erf(c2), gelu_erf(c3));
                *reinterpret_cast<__half2*>(dst + sw128((uint32_t)lrow * 128 + cb))       = v01;
                *reinterpret_cast<__half2*>(dst + sw128((uint32_t)(lrow + 8) * 128 + cb)) = v23;
            } else {
                float* o = (float*)out;
                size_t r0 = (size_t)(bm + lrow) * OUT_DIM + col;
                *reinterpret_cast<float2*>(o + r0)                       = make_float2(c0, c1);
                *reinterpret_cast<float2*>(o + r0 + (size_t)8 * OUT_DIM) = make_float2(c2, c3);
            }
        }
    }
}

// ---------------------------------------------------------------------------
// launch
// ---------------------------------------------------------------------------
extern "C" void kernel_launch(void* const* d_in, const int* in_sizes, int n_in,
                              void* d_out, int out_size) {
    const int*   d_idx = (const int*)  d_in[0];
    const float* d_x   = (const float*)d_in[1];
    const float* d_W1  = (const float*)d_in[2];
    const float* d_W2  = (const float*)d_in[3];

    __half *px, *pw1, *pw2, *ph;
    cudaGetSymbolAddress((void**)&px,  g_x);
    cudaGetSymbolAddress((void**)&pw1, g_w1);
    cudaGetSymbolAddress((void**)&pw2, g_w2);
    cudaGetSymbolAddress((void**)&ph,  g_h);

    cudaFuncSetAttribute((const void*)hmma_gemm<true, 32, 64>,
                         cudaFuncAttributeMaxDynamicSharedMemorySize, SMEM_BYTES);
    cudaFuncSetAttribute((const void*)hmma_gemm<false, 64, 0>,
                         cudaFuncAttributeMaxDynamicSharedMemorySize, SMEM_BYTES);

    // 1) x -> tiled fp16 (KT=32)
    {
        size_t ng = (size_t)M_NODES * IN_DIM / 8;
        cvt_tiled<<<(unsigned)((ng + 255) / 256), 256>>>(d_x, nullptr, 0, px, IN_DIM, IN_DIM / 64, ng);
    }
    // 2) W1[e] -> tiled fp16 (KT=32)
    {
        size_t pe = (size_t)HID_DIM * IN_DIM;
        size_t ng = pe / 8;
        cvt_tiled<<<(unsigned)((ng + 255) / 256), 256>>>(d_W1, d_idx, pe, pw1, IN_DIM, IN_DIM / 64, ng);
    }
    // 3) W2[e] -> tiled fp16 (KT=64)
    {
        size_t pe = (size_t)OUT_DIM * HID_DIM;
        size_t ng = pe / 8;
        cvt_tiled<<<(unsigned)((ng + 255) / 256), 256>>>(d_W2, d_idx, pe, pw2, HID_DIM, HID_DIM / 64, ng);
    }
    // 4) h = gelu(x @ W1^T) -> tiled fp16, dst KT=64
    {
        dim3 grid(HID_DIM / 128, M_NODES / 128);
        hmma_gemm<true, 32, 64><<<grid, 256, SMEM_BYTES>>>((const char*)px, (const char*)pw1, ph);
    }
    // 5) out = h @ W2^T -> fp32 row-major
    {
        dim3 grid(OUT_DIM / 128, M_NODES / 128);
        hmma_gemm<false, 64, 0><<<grid, 256, SMEM_BYTES>>>((const char*)ph, (const char*)pw2, d_out);
    }
}